// round 1
// baseline (speedup 1.0000x reference)
#include <cuda_runtime.h>
#include <stdint.h>

#define M_TOT 16384
#define HDIM_ 2048
#define IDIM_ 512
#define ODIM_ 512

// 128 MiB scratch for the hidden activation h (B*T x HDIM)
__device__ float g_h[(size_t)M_TOT * HDIM_];

// ---------------------------------------------------------------------------
// Tiled SGEMM: C[M,N] = A[M,K] * B[N,K]^T + bias[N]
// Both A and B are K-contiguous (row-major with K as the fast dim).
// FUSE_MASK: zero output where maskPrev > 0 (encoder epilogue).
// 128x128 block tile, 16 K-tile, 256 threads, 8x8 per thread.
// ---------------------------------------------------------------------------
template<bool FUSE_MASK>
__global__ __launch_bounds__(256)
void sgemm_nt(const float* __restrict__ A,
              const float* __restrict__ B,
              const float* __restrict__ bias,
              const int*   __restrict__ maskPrev,
              float* __restrict__ C,
              int M, int N, int K)
{
    __shared__ float As[16][128];
    __shared__ float Bs[16][128];

    const int tid = threadIdx.x;
    const int m0 = blockIdx.y * 128;
    const int n0 = blockIdx.x * 128;
    const int tx = tid & 15;   // 0..15 -> 8 output cols each
    const int ty = tid >> 4;   // 0..15 -> 8 output rows each

    float acc[8][8];
#pragma unroll
    for (int i = 0; i < 8; ++i)
#pragma unroll
        for (int j = 0; j < 8; ++j) acc[i][j] = 0.f;

    const float* Ab = A + (size_t)m0 * K;
    const float* Bb = B + (size_t)n0 * K;

    const int lrow = tid >> 2;        // 0..63
    const int lk   = (tid & 3) << 2;  // 0,4,8,12

    for (int kt = 0; kt < K; kt += 16) {
        float4 a0 = *(const float4*)(Ab + (size_t)lrow        * K + kt + lk);
        float4 a1 = *(const float4*)(Ab + (size_t)(lrow + 64) * K + kt + lk);
        float4 b0 = *(const float4*)(Bb + (size_t)lrow        * K + kt + lk);
        float4 b1 = *(const float4*)(Bb + (size_t)(lrow + 64) * K + kt + lk);

        As[lk + 0][lrow] = a0.x; As[lk + 1][lrow] = a0.y;
        As[lk + 2][lrow] = a0.z; As[lk + 3][lrow] = a0.w;
        As[lk + 0][lrow + 64] = a1.x; As[lk + 1][lrow + 64] = a1.y;
        As[lk + 2][lrow + 64] = a1.z; As[lk + 3][lrow + 64] = a1.w;
        Bs[lk + 0][lrow] = b0.x; Bs[lk + 1][lrow] = b0.y;
        Bs[lk + 2][lrow] = b0.z; Bs[lk + 3][lrow] = b0.w;
        Bs[lk + 0][lrow + 64] = b1.x; Bs[lk + 1][lrow + 64] = b1.y;
        Bs[lk + 2][lrow + 64] = b1.z; Bs[lk + 3][lrow + 64] = b1.w;
        __syncthreads();

#pragma unroll
        for (int k = 0; k < 16; ++k) {
            float a[8], b[8];
            *(float4*)&a[0] = *(const float4*)&As[k][ty * 8];
            *(float4*)&a[4] = *(const float4*)&As[k][ty * 8 + 4];
            *(float4*)&b[0] = *(const float4*)&Bs[k][tx * 8];
            *(float4*)&b[4] = *(const float4*)&Bs[k][tx * 8 + 4];
#pragma unroll
            for (int i = 0; i < 8; ++i)
#pragma unroll
                for (int j = 0; j < 8; ++j)
                    acc[i][j] = fmaf(a[i], b[j], acc[i][j]);
        }
        __syncthreads();
    }

    float bcol[8];
#pragma unroll
    for (int j = 0; j < 8; ++j) bcol[j] = bias[n0 + tx * 8 + j];

#pragma unroll
    for (int i = 0; i < 8; ++i) {
        const size_t m = (size_t)(m0 + ty * 8 + i);
#pragma unroll
        for (int jq = 0; jq < 8; jq += 4) {
            float4 v;
            v.x = acc[i][jq + 0] + bcol[jq + 0];
            v.y = acc[i][jq + 1] + bcol[jq + 1];
            v.z = acc[i][jq + 2] + bcol[jq + 2];
            v.w = acc[i][jq + 3] + bcol[jq + 3];
            const size_t cidx = m * (size_t)N + (size_t)(n0 + tx * 8 + jq);
            if (FUSE_MASK) {
                int4 mp = *(const int4*)(maskPrev + cidx);
                if (mp.x > 0) v.x = 0.f;
                if (mp.y > 0) v.y = 0.f;
                if (mp.z > 0) v.z = 0.f;
                if (mp.w > 0) v.w = 0.f;
            }
            *(float4*)(C + cidx) = v;
        }
    }
}

// ---------------------------------------------------------------------------
// Per-row exact top-k selection over h^2 (k=512 -> mask_share, k=256 -> mask_cur)
// via 4-pass 8-bit radix select on the uint bit pattern of h*h (monotone for
// non-negative floats). Ties broken by lowest index (matches XLA stable sort).
// Writes: g_h *= mask_share (in place); maskNew = mask_prev + mask_cur.
// One block of 256 threads per row (2048 channels).
// ---------------------------------------------------------------------------
__global__ __launch_bounds__(256)
void topk_mask_kernel(const int* __restrict__ maskPrev,
                      float* __restrict__ maskNew)
{
    __shared__ float    sh[HDIM_];
    __shared__ unsigned s_hist[256];
    __shared__ unsigned s_scan[256];
    __shared__ unsigned s_pick[2];

    const int row = blockIdx.x;
    const int tid = threadIdx.x;
    float* __restrict__ hrow = g_h + (size_t)row * HDIM_;

#pragma unroll
    for (int i = 0; i < 2; ++i) {
        int c = (tid + i * 256) * 4;
        *(float4*)&sh[c] = *(const float4*)&hrow[c];
    }
    __syncthreads();

    unsigned T[2], R[2];

#pragma unroll 1
    for (int sel = 0; sel < 2; ++sel) {
        unsigned kk = (sel == 0) ? 512u : 256u;
        unsigned prefix = 0u, pmask = 0u;
#pragma unroll 1
        for (int pass = 0; pass < 4; ++pass) {
            const int shift = 24 - 8 * pass;
            s_hist[tid] = 0u;
            __syncthreads();
#pragma unroll
            for (int j = 0; j < 8; ++j) {
                float v = sh[tid * 8 + j];
                unsigned u = __float_as_uint(v * v);
                if ((u & pmask) == prefix)
                    atomicAdd(&s_hist[(u >> shift) & 255u], 1u);
            }
            __syncthreads();
            unsigned cnt = s_hist[tid];
            s_scan[tid] = cnt;
            __syncthreads();
            // suffix (descending) inclusive scan: s_scan[b] = sum_{j>=b} hist[j]
            for (int off = 1; off < 256; off <<= 1) {
                unsigned v = (tid + off < 256) ? s_scan[tid + off] : 0u;
                __syncthreads();
                s_scan[tid] += v;
                __syncthreads();
            }
            unsigned suf  = s_scan[tid];
            unsigned sufn = (tid < 255) ? s_scan[tid + 1] : 0u;
            if (suf >= kk && sufn < kk) {   // unique winner bin
                s_pick[0] = (unsigned)tid;
                s_pick[1] = kk - sufn;      // still needed from == this digit
            }
            __syncthreads();
            prefix |= s_pick[0] << shift;
            pmask  |= 255u << shift;
            kk = s_pick[1];
            __syncthreads();
        }
        T[sel] = prefix;   // bit pattern of the k-th largest h^2
        R[sel] = kk;       // how many ==T elements to take (lowest index first)
    }

    // Rank elements equal to each threshold by index (packed two 16-bit counts)
    unsigned c0 = 0, c1 = 0;
#pragma unroll
    for (int j = 0; j < 8; ++j) {
        float v = sh[tid * 8 + j];
        unsigned u = __float_as_uint(v * v);
        c0 += (u == T[0]);
        c1 += (u == T[1]);
    }
    s_scan[tid] = (c0 << 16) | c1;
    __syncthreads();
    for (int off = 1; off < 256; off <<= 1) {
        unsigned v = (tid >= off) ? s_scan[tid - off] : 0u;
        __syncthreads();
        s_scan[tid] += v;
        __syncthreads();
    }
    unsigned incl = s_scan[tid];
    unsigned r0 = (incl >> 16)    - c0;   // exclusive rank among ==T[0]
    unsigned r1 = (incl & 0xFFFF) - c1;   // exclusive rank among ==T[1]

    const int* __restrict__ mrow = maskPrev + (size_t)row * HDIM_;
    float*     __restrict__ nrow = maskNew  + (size_t)row * HDIM_;
#pragma unroll
    for (int j = 0; j < 8; ++j) {
        int c = tid * 8 + j;
        float v = sh[c];
        unsigned u = __float_as_uint(v * v);
        unsigned eq0 = (u == T[0]) ? 1u : 0u;
        bool share = (u > T[0]) || (eq0 && r0 < R[0]);
        r0 += eq0;
        unsigned eq1 = (u == T[1]) ? 1u : 0u;
        bool cur = (u > T[1]) || (eq1 && r1 < R[1]);
        r1 += eq1;
        hrow[c] = share ? v : 0.f;
        nrow[c] = (float)mrow[c] + (cur ? 1.f : 0.f);
    }
}

// ---------------------------------------------------------------------------
extern "C" void kernel_launch(void* const* d_in, const int* in_sizes, int n_in,
                              void* d_out, int out_size)
{
    const float* x      = (const float*)d_in[0];  // [8,2048,512]
    const int*   mask_p = (const int*)  d_in[1];  // [8,2048,2048]
    const float* W_enc  = (const float*)d_in[2];  // [2048,512]
    const float* b_enc  = (const float*)d_in[3];  // [2048]
    const float* W_dec  = (const float*)d_in[4];  // [512,2048]
    const float* b_dec  = (const float*)d_in[5];  // [512]

    float* out      = (float*)d_out;                       // [8,2048,512]
    float* mask_new = out + (size_t)M_TOT * ODIM_;         // [8,2048,2048]

    float* hbuf = nullptr;
    cudaGetSymbolAddress((void**)&hbuf, g_h);

    dim3 blk(256);
    // h = x @ W_enc^T + b_enc, zeroed where mask_prev > 0
    sgemm_nt<true ><<<dim3(HDIM_ / 128, M_TOT / 128), blk>>>(
        x, W_enc, b_enc, mask_p, hbuf, M_TOT, HDIM_, IDIM_);
    // top-k masks + h *= mask_share + mask_prev_new
    topk_mask_kernel<<<M_TOT, blk>>>(mask_p, mask_new);
    // out = h_masked @ W_dec^T + b_dec
    sgemm_nt<false><<<dim3(ODIM_ / 128, M_TOT / 128), blk>>>(
        hbuf, W_dec, b_dec, nullptr, out, M_TOT, ODIM_, HDIM_);
}

// round 2
// speedup vs baseline: 1.0015x; 1.0015x over previous
#include <cuda_runtime.h>
#include <stdint.h>

#define M_TOT 16384
#define HDIM_ 2048
#define IDIM_ 512
#define ODIM_ 512

// 128 MiB scratch for the hidden activation h (B*T x HDIM)
__device__ float g_h[(size_t)M_TOT * HDIM_];

// ---------------------------------------------------------------------------
// Tiled SGEMM: C[M,N] = A[M,K] * B[N,K]^T + bias[N]
// Both A and B are K-contiguous (row-major with K as the fast dim).
// FUSE_MASK: zero output where maskPrev > 0 (encoder epilogue).
// 128x128 block tile, 16 K-tile, 256 threads, 8x8 per thread.
// ---------------------------------------------------------------------------
template<bool FUSE_MASK>
__global__ __launch_bounds__(256)
void sgemm_nt(const float* __restrict__ A,
              const float* __restrict__ B,
              const float* __restrict__ bias,
              const int*   __restrict__ maskPrev,
              float* __restrict__ C,
              int M, int N, int K)
{
    __shared__ float As[16][128];
    __shared__ float Bs[16][128];

    const int tid = threadIdx.x;
    const int m0 = blockIdx.y * 128;
    const int n0 = blockIdx.x * 128;
    const int tx = tid & 15;   // 0..15 -> 8 output cols each
    const int ty = tid >> 4;   // 0..15 -> 8 output rows each

    float acc[8][8];
#pragma unroll
    for (int i = 0; i < 8; ++i)
#pragma unroll
        for (int j = 0; j < 8; ++j) acc[i][j] = 0.f;

    const float* Ab = A + (size_t)m0 * K;
    const float* Bb = B + (size_t)n0 * K;

    const int lrow = tid >> 2;        // 0..63
    const int lk   = (tid & 3) << 2;  // 0,4,8,12

    for (int kt = 0; kt < K; kt += 16) {
        float4 a0 = *(const float4*)(Ab + (size_t)lrow        * K + kt + lk);
        float4 a1 = *(const float4*)(Ab + (size_t)(lrow + 64) * K + kt + lk);
        float4 b0 = *(const float4*)(Bb + (size_t)lrow        * K + kt + lk);
        float4 b1 = *(const float4*)(Bb + (size_t)(lrow + 64) * K + kt + lk);

        As[lk + 0][lrow] = a0.x; As[lk + 1][lrow] = a0.y;
        As[lk + 2][lrow] = a0.z; As[lk + 3][lrow] = a0.w;
        As[lk + 0][lrow + 64] = a1.x; As[lk + 1][lrow + 64] = a1.y;
        As[lk + 2][lrow + 64] = a1.z; As[lk + 3][lrow + 64] = a1.w;
        Bs[lk + 0][lrow] = b0.x; Bs[lk + 1][lrow] = b0.y;
        Bs[lk + 2][lrow] = b0.z; Bs[lk + 3][lrow] = b0.w;
        Bs[lk + 0][lrow + 64] = b1.x; Bs[lk + 1][lrow + 64] = b1.y;
        Bs[lk + 2][lrow + 64] = b1.z; Bs[lk + 3][lrow + 64] = b1.w;
        __syncthreads();

#pragma unroll
        for (int k = 0; k < 16; ++k) {
            float a[8], b[8];
            *(float4*)&a[0] = *(const float4*)&As[k][ty * 8];
            *(float4*)&a[4] = *(const float4*)&As[k][ty * 8 + 4];
            *(float4*)&b[0] = *(const float4*)&Bs[k][tx * 8];
            *(float4*)&b[4] = *(const float4*)&Bs[k][tx * 8 + 4];
#pragma unroll
            for (int i = 0; i < 8; ++i)
#pragma unroll
                for (int j = 0; j < 8; ++j)
                    acc[i][j] = fmaf(a[i], b[j], acc[i][j]);
        }
        __syncthreads();
    }

    float bcol[8];
#pragma unroll
    for (int j = 0; j < 8; ++j) bcol[j] = bias[n0 + tx * 8 + j];

#pragma unroll
    for (int i = 0; i < 8; ++i) {
        const size_t m = (size_t)(m0 + ty * 8 + i);
#pragma unroll
        for (int jq = 0; jq < 8; jq += 4) {
            float4 v;
            v.x = acc[i][jq + 0] + bcol[jq + 0];
            v.y = acc[i][jq + 1] + bcol[jq + 1];
            v.z = acc[i][jq + 2] + bcol[jq + 2];
            v.w = acc[i][jq + 3] + bcol[jq + 3];
            const size_t cidx = m * (size_t)N + (size_t)(n0 + tx * 8 + jq);
            if (FUSE_MASK) {
                int4 mp = *(const int4*)(maskPrev + cidx);
                if (mp.x > 0) v.x = 0.f;
                if (mp.y > 0) v.y = 0.f;
                if (mp.z > 0) v.z = 0.f;
                if (mp.w > 0) v.w = 0.f;
            }
            *(float4*)(C + cidx) = v;
        }
    }
}

// ---------------------------------------------------------------------------
// Per-row exact top-k selection over h^2 (k=512 -> mask_share, k=256 -> mask_cur)
// via 4-pass 8-bit radix select on the uint bit pattern of h*h (monotone for
// non-negative floats). Ties broken by lowest index (matches XLA stable sort).
// Writes: g_h *= mask_share (in place); maskNew = mask_prev + mask_cur.
// One block of 256 threads per row (2048 channels).
// ---------------------------------------------------------------------------
__global__ __launch_bounds__(256)
void topk_mask_kernel(const int* __restrict__ maskPrev,
                      float* __restrict__ maskNew)
{
    __shared__ float    sh[HDIM_];
    __shared__ unsigned s_hist[256];
    __shared__ unsigned s_scan[256];
    __shared__ unsigned s_pick[2];

    const int row = blockIdx.x;
    const int tid = threadIdx.x;
    float* __restrict__ hrow = g_h + (size_t)row * HDIM_;

#pragma unroll
    for (int i = 0; i < 2; ++i) {
        int c = (tid + i * 256) * 4;
        *(float4*)&sh[c] = *(const float4*)&hrow[c];
    }
    __syncthreads();

    unsigned T[2], R[2];

#pragma unroll 1
    for (int sel = 0; sel < 2; ++sel) {
        unsigned kk = (sel == 0) ? 512u : 256u;
        unsigned prefix = 0u, pmask = 0u;
#pragma unroll 1
        for (int pass = 0; pass < 4; ++pass) {
            const int shift = 24 - 8 * pass;
            s_hist[tid] = 0u;
            __syncthreads();
#pragma unroll
            for (int j = 0; j < 8; ++j) {
                float v = sh[tid * 8 + j];
                unsigned u = __float_as_uint(v * v);
                if ((u & pmask) == prefix)
                    atomicAdd(&s_hist[(u >> shift) & 255u], 1u);
            }
            __syncthreads();
            unsigned cnt = s_hist[tid];
            s_scan[tid] = cnt;
            __syncthreads();
            // suffix (descending) inclusive scan: s_scan[b] = sum_{j>=b} hist[j]
            for (int off = 1; off < 256; off <<= 1) {
                unsigned v = (tid + off < 256) ? s_scan[tid + off] : 0u;
                __syncthreads();
                s_scan[tid] += v;
                __syncthreads();
            }
            unsigned suf  = s_scan[tid];
            unsigned sufn = (tid < 255) ? s_scan[tid + 1] : 0u;
            if (suf >= kk && sufn < kk) {   // unique winner bin
                s_pick[0] = (unsigned)tid;
                s_pick[1] = kk - sufn;      // still needed from == this digit
            }
            __syncthreads();
            prefix |= s_pick[0] << shift;
            pmask  |= 255u << shift;
            kk = s_pick[1];
            __syncthreads();
        }
        T[sel] = prefix;   // bit pattern of the k-th largest h^2
        R[sel] = kk;       // how many ==T elements to take (lowest index first)
    }

    // Rank elements equal to each threshold by index (packed two 16-bit counts)
    unsigned c0 = 0, c1 = 0;
#pragma unroll
    for (int j = 0; j < 8; ++j) {
        float v = sh[tid * 8 + j];
        unsigned u = __float_as_uint(v * v);
        c0 += (u == T[0]);
        c1 += (u == T[1]);
    }
    s_scan[tid] = (c0 << 16) | c1;
    __syncthreads();
    for (int off = 1; off < 256; off <<= 1) {
        unsigned v = (tid >= off) ? s_scan[tid - off] : 0u;
        __syncthreads();
        s_scan[tid] += v;
        __syncthreads();
    }
    unsigned incl = s_scan[tid];
    unsigned r0 = (incl >> 16)    - c0;   // exclusive rank among ==T[0]
    unsigned r1 = (incl & 0xFFFF) - c1;   // exclusive rank among ==T[1]

    const int* __restrict__ mrow = maskPrev + (size_t)row * HDIM_;
    float*     __restrict__ nrow = maskNew  + (size_t)row * HDIM_;
#pragma unroll
    for (int j = 0; j < 8; ++j) {
        int c = tid * 8 + j;
        float v = sh[c];
        unsigned u = __float_as_uint(v * v);
        unsigned eq0 = (u == T[0]) ? 1u : 0u;
        bool share = (u > T[0]) || (eq0 && r0 < R[0]);
        r0 += eq0;
        unsigned eq1 = (u == T[1]) ? 1u : 0u;
        bool cur = (u > T[1]) || (eq1 && r1 < R[1]);
        r1 += eq1;
        hrow[c] = share ? v : 0.f;
        nrow[c] = (float)mrow[c] + (cur ? 1.f : 0.f);
    }
}

// ---------------------------------------------------------------------------
extern "C" void kernel_launch(void* const* d_in, const int* in_sizes, int n_in,
                              void* d_out, int out_size)
{
    const float* x      = (const float*)d_in[0];  // [8,2048,512]
    const int*   mask_p = (const int*)  d_in[1];  // [8,2048,2048]
    const float* W_enc  = (const float*)d_in[2];  // [2048,512]
    const float* b_enc  = (const float*)d_in[3];  // [2048]
    const float* W_dec  = (const float*)d_in[4];  // [512,2048]
    const float* b_dec  = (const float*)d_in[5];  // [512]

    float* out      = (float*)d_out;                       // [8,2048,512]
    float* mask_new = out + (size_t)M_TOT * ODIM_;         // [8,2048,2048]

    float* hbuf = nullptr;
    cudaGetSymbolAddress((void**)&hbuf, g_h);

    dim3 blk(256);
    // h = x @ W_enc^T + b_enc, zeroed where mask_prev > 0
    sgemm_nt<true ><<<dim3(HDIM_ / 128, M_TOT / 128), blk>>>(
        x, W_enc, b_enc, mask_p, hbuf, M_TOT, HDIM_, IDIM_);
    // top-k masks + h *= mask_share + mask_prev_new
    topk_mask_kernel<<<M_TOT, blk>>>(mask_p, mask_new);
    // out = h_masked @ W_dec^T + b_dec
    sgemm_nt<false><<<dim3(ODIM_ / 128, M_TOT / 128), blk>>>(
        hbuf, W_dec, b_dec, nullptr, out, M_TOT, ODIM_, HDIM_);
}

// round 5
// speedup vs baseline: 1.5203x; 1.5179x over previous
#include <cuda_runtime.h>
#include <cuda_bf16.h>
#include <stdint.h>

#define M_TOT 16384
#define HDIM_ 2048
#define IDIM_ 512
#define ODIM_ 512

// scratch (device globals; no allocs allowed)
__device__ float         g_h  [(size_t)M_TOT * HDIM_];
__device__ __nv_bfloat16 g_hb0[(size_t)M_TOT * HDIM_];
__device__ __nv_bfloat16 g_hb1[(size_t)M_TOT * HDIM_];
__device__ __nv_bfloat16 g_wd0[(size_t)ODIM_ * HDIM_];
__device__ __nv_bfloat16 g_wd1[(size_t)ODIM_ * HDIM_];

__device__ __forceinline__ uint32_t smem_u32(const void* p){
    uint32_t a;
    asm("{ .reg .u64 t; cvta.to.shared.u64 t, %1; cvt.u32.u64 %0, t; }" : "=r"(a) : "l"(p));
    return a;
}
#define CP16(d, s) asm volatile("cp.async.cg.shared.global [%0], [%1], 16;" :: "r"(d), "l"(s))
#define CP_COMMIT() asm volatile("cp.async.commit_group;")
#define CP_WAIT1()  asm volatile("cp.async.wait_group 1;")

// ---------------------------------------------------------------------------
// Encoder: R1's FFMA SGEMM (known-good numerics for the top-k).
// C[M,N] = A[M,K] * B[N,K]^T + bias[N], zero where maskPrev>0.
// ---------------------------------------------------------------------------
__global__ __launch_bounds__(256)
void sgemm_nt_mask(const float* __restrict__ A,
                   const float* __restrict__ B,
                   const float* __restrict__ bias,
                   const int*   __restrict__ maskPrev,
                   float* __restrict__ C,
                   int M, int N, int K)
{
    __shared__ float As[16][128];
    __shared__ float Bs[16][128];

    const int tid = threadIdx.x;
    const int m0 = blockIdx.y * 128;
    const int n0 = blockIdx.x * 128;
    const int tx = tid & 15;
    const int ty = tid >> 4;

    float acc[8][8];
#pragma unroll
    for (int i = 0; i < 8; ++i)
#pragma unroll
        for (int j = 0; j < 8; ++j) acc[i][j] = 0.f;

    const float* Ab = A + (size_t)m0 * K;
    const float* Bb = B + (size_t)n0 * K;

    const int lrow = tid >> 2;
    const int lk   = (tid & 3) << 2;

    for (int kt = 0; kt < K; kt += 16) {
        float4 a0 = *(const float4*)(Ab + (size_t)lrow        * K + kt + lk);
        float4 a1 = *(const float4*)(Ab + (size_t)(lrow + 64) * K + kt + lk);
        float4 b0 = *(const float4*)(Bb + (size_t)lrow        * K + kt + lk);
        float4 b1 = *(const float4*)(Bb + (size_t)(lrow + 64) * K + kt + lk);

        As[lk + 0][lrow] = a0.x; As[lk + 1][lrow] = a0.y;
        As[lk + 2][lrow] = a0.z; As[lk + 3][lrow] = a0.w;
        As[lk + 0][lrow + 64] = a1.x; As[lk + 1][lrow + 64] = a1.y;
        As[lk + 2][lrow + 64] = a1.z; As[lk + 3][lrow + 64] = a1.w;
        Bs[lk + 0][lrow] = b0.x; Bs[lk + 1][lrow] = b0.y;
        Bs[lk + 2][lrow] = b0.z; Bs[lk + 3][lrow] = b0.w;
        Bs[lk + 0][lrow + 64] = b1.x; Bs[lk + 1][lrow + 64] = b1.y;
        Bs[lk + 2][lrow + 64] = b1.z; Bs[lk + 3][lrow + 64] = b1.w;
        __syncthreads();

#pragma unroll
        for (int k = 0; k < 16; ++k) {
            float a[8], b[8];
            *(float4*)&a[0] = *(const float4*)&As[k][ty * 8];
            *(float4*)&a[4] = *(const float4*)&As[k][ty * 8 + 4];
            *(float4*)&b[0] = *(const float4*)&Bs[k][tx * 8];
            *(float4*)&b[4] = *(const float4*)&Bs[k][tx * 8 + 4];
#pragma unroll
            for (int i = 0; i < 8; ++i)
#pragma unroll
                for (int j = 0; j < 8; ++j)
                    acc[i][j] = fmaf(a[i], b[j], acc[i][j]);
        }
        __syncthreads();
    }

    float bcol[8];
#pragma unroll
    for (int j = 0; j < 8; ++j) bcol[j] = bias[n0 + tx * 8 + j];

#pragma unroll
    for (int i = 0; i < 8; ++i) {
        const size_t m = (size_t)(m0 + ty * 8 + i);
#pragma unroll
        for (int jq = 0; jq < 8; jq += 4) {
            float4 v;
            v.x = acc[i][jq + 0] + bcol[jq + 0];
            v.y = acc[i][jq + 1] + bcol[jq + 1];
            v.z = acc[i][jq + 2] + bcol[jq + 2];
            v.w = acc[i][jq + 3] + bcol[jq + 3];
            const size_t cidx = m * (size_t)N + (size_t)(n0 + tx * 8 + jq);
            const int4 mp = *(const int4*)(maskPrev + cidx);
            if (mp.x > 0) v.x = 0.f;
            if (mp.y > 0) v.y = 0.f;
            if (mp.z > 0) v.z = 0.f;
            if (mp.w > 0) v.w = 0.f;
            *(float4*)(C + cidx) = v;
        }
    }
}

// ---------------------------------------------------------------------------
// Decoder: bf16 4-product mma.sync (m16n8k16). Inputs are exact 2-plane bf16
// splits (x = b0 + b1 + O(2^-16 x)); products b0b0+b0b1+b1b0+b1b1 -> ~3e-5 err.
// C[M,N] = A[M,K]*B[N,K]^T + bias[N].
// ---------------------------------------------------------------------------
__device__ __forceinline__ void mma_bf16(float* c, const uint32_t* a, uint32_t b0, uint32_t b1){
    asm volatile("mma.sync.aligned.m16n8k16.row.col.f32.bf16.bf16.f32 "
        "{%0,%1,%2,%3},{%4,%5,%6,%7},{%8,%9},{%0,%1,%2,%3};"
        : "+f"(c[0]), "+f"(c[1]), "+f"(c[2]), "+f"(c[3])
        : "r"(a[0]), "r"(a[1]), "r"(a[2]), "r"(a[3]), "r"(b0), "r"(b1));
}

static constexpr int LDTH    = 40;            // halfs per smem row (32 + 8 pad) -> conflict-free
static constexpr int PLANE_H = 128 * LDTH;    // 5120 halfs
static constexpr int PLANE_B = PLANE_H * 2;   // 10240 bytes
static constexpr int STAGE_B = 4 * PLANE_B;   // planes A0,A1,B0,B1 = 40960 bytes
static constexpr int BIAS_B  = 2 * STAGE_B;   // 81920
static constexpr int SMEM_DEC = BIAS_B + 512; // + 128 floats bias

__global__ __launch_bounds__(256, 1)
void gemm_bf4(const __nv_bfloat16* __restrict__ A0, const __nv_bfloat16* __restrict__ A1,
              const __nv_bfloat16* __restrict__ B0, const __nv_bfloat16* __restrict__ B1,
              const float* __restrict__ bias, float* __restrict__ C,
              int M, int N, int K)
{
    extern __shared__ char smem[];
    const uint32_t sb = smem_u32(smem);
    const int tid = threadIdx.x;
    const int lane = tid & 31, wid = tid >> 5;
    const int wm = wid & 3, wn = wid >> 2;        // 4 m-warps x 2 n-warps (tile 32x64)
    const int g = lane >> 2, t4 = lane & 3;
    const int m0 = blockIdx.y * 128, n0 = blockIdx.x * 128;

    float* sbias = (float*)(smem + BIAS_B);
    if (tid < 128) sbias[tid] = bias[n0 + tid];

    // staging: thread -> row = tid>>1, 32-byte half-chunk = (tid&1)
    const int lr  = tid >> 1;
    const int lcb = (tid & 1) * 32;               // byte offset in the 64B row chunk
    const __nv_bfloat16* pA0 = A0 + (size_t)(m0 + lr) * K;
    const __nv_bfloat16* pA1 = A1 + (size_t)(m0 + lr) * K;
    const __nv_bfloat16* pB0 = B0 + (size_t)(n0 + lr) * K;
    const __nv_bfloat16* pB1 = B1 + (size_t)(n0 + lr) * K;
    const uint32_t dof = (uint32_t)(lr * (LDTH * 2) + lcb);

    auto load_stage = [&](int kt, int s) {
        const uint32_t base = sb + (uint32_t)(s * STAGE_B) + dof;
        const int ko = kt * 32 + (lcb >> 1);      // half offset
        CP16(base,                 pA0 + ko); CP16(base + 16,                 pA0 + ko + 8);
        CP16(base + PLANE_B,       pA1 + ko); CP16(base + PLANE_B + 16,       pA1 + ko + 8);
        CP16(base + 2 * PLANE_B,   pB0 + ko); CP16(base + 2 * PLANE_B + 16,   pB0 + ko + 8);
        CP16(base + 3 * PLANE_B,   pB1 + ko); CP16(base + 3 * PLANE_B + 16,   pB1 + ko + 8);
    };

    float acc[2][8][4];
#pragma unroll
    for (int a = 0; a < 2; ++a)
#pragma unroll
        for (int b = 0; b < 8; ++b)
#pragma unroll
            for (int q = 0; q < 4; ++q) acc[a][b][q] = 0.f;

    load_stage(0, 0); CP_COMMIT();
    load_stage(1, 1); CP_COMMIT();

    const int KT = K >> 5;                        // 32-wide K chunks
    for (int kt = 0; kt < KT; ++kt) {
        const int s = kt & 1;
        CP_WAIT1();
        __syncthreads();
        const __nv_bfloat16* st = (const __nv_bfloat16*)(smem + s * STAGE_B);
#pragma unroll
        for (int ks = 0; ks < 2; ++ks) {
            uint32_t af[2][2][4];                 // [plane][mt][frag]
#pragma unroll
            for (int p = 0; p < 2; ++p)
#pragma unroll
                for (int mt = 0; mt < 2; ++mt) {
                    const int off = p * PLANE_H + (wm * 32 + mt * 16 + g) * LDTH + ks * 16 + 2 * t4;
                    af[p][mt][0] = *(const uint32_t*)(st + off);
                    af[p][mt][1] = *(const uint32_t*)(st + off + 8 * LDTH);
                    af[p][mt][2] = *(const uint32_t*)(st + off + 8);
                    af[p][mt][3] = *(const uint32_t*)(st + off + 8 * LDTH + 8);
                }
#pragma unroll
            for (int nt = 0; nt < 8; ++nt) {
                const int boff = (wn * 64 + nt * 8 + g) * LDTH + ks * 16 + 2 * t4;
                const uint32_t b00 = *(const uint32_t*)(st + 2 * PLANE_H + boff);
                const uint32_t b01 = *(const uint32_t*)(st + 2 * PLANE_H + boff + 8);
                const uint32_t b10 = *(const uint32_t*)(st + 3 * PLANE_H + boff);
                const uint32_t b11 = *(const uint32_t*)(st + 3 * PLANE_H + boff + 8);
#pragma unroll
                for (int mt = 0; mt < 2; ++mt) {
                    mma_bf16(acc[mt][nt], af[0][mt], b00, b01);
                    mma_bf16(acc[mt][nt], af[0][mt], b10, b11);
                    mma_bf16(acc[mt][nt], af[1][mt], b00, b01);
                    mma_bf16(acc[mt][nt], af[1][mt], b10, b11);
                }
            }
        }
        __syncthreads();
        if (kt + 2 < KT) load_stage(kt + 2, s);
        CP_COMMIT();
    }

#pragma unroll
    for (int mt = 0; mt < 2; ++mt) {
#pragma unroll
        for (int nt = 0; nt < 8; ++nt) {
            const int rr = m0 + wm * 32 + mt * 16 + g;
            const int cl = wn * 64 + nt * 8 + 2 * t4;
            const float b0 = sbias[cl];
            const float b1 = sbias[cl + 1];
            const float* c = acc[mt][nt];
            const size_t i0 = (size_t)rr * N + (n0 + cl);
            const size_t i1 = (size_t)(rr + 8) * N + (n0 + cl);
            *(float2*)(C + i0) = make_float2(c[0] + b0, c[1] + b1);
            *(float2*)(C + i1) = make_float2(c[2] + b0, c[3] + b1);
        }
    }
}

// fp32 -> 2-plane bf16 split (exact to 2^-16)
__global__ __launch_bounds__(256)
void split_bf2(const float* __restrict__ src, __nv_bfloat16* __restrict__ p0,
               __nv_bfloat16* __restrict__ p1, int n8)
{
    int i = blockIdx.x * 256 + threadIdx.x;
    if (i >= n8) return;
    float4 v0 = ((const float4*)src)[2 * i];
    float4 v1 = ((const float4*)src)[2 * i + 1];
    float x[8] = {v0.x, v0.y, v0.z, v0.w, v1.x, v1.y, v1.z, v1.w};
    __nv_bfloat16 b0[8], b1[8];
#pragma unroll
    for (int j = 0; j < 8; ++j) {
        b0[j] = __float2bfloat16_rn(x[j]);
        b1[j] = __float2bfloat16_rn(x[j] - __bfloat162float(b0[j]));
    }
    ((uint4*)p0)[i] = *(uint4*)b0;
    ((uint4*)p1)[i] = *(uint4*)b1;
}

// ---------------------------------------------------------------------------
// Per-row exact dual top-k (512/256) over h^2; radix select on bits of v*v,
// lowest-index tie break. Emits mask_new and masked-h as 2 bf16 planes.
// ---------------------------------------------------------------------------
__global__ __launch_bounds__(256)
void topk_mask_kernel(const int* __restrict__ maskPrev, float* __restrict__ maskNew)
{
    __shared__ unsigned s_hist[256];
    __shared__ unsigned s_warp[8];
    __shared__ unsigned s_wsuf[8];
    __shared__ unsigned s_pick[2];

    const int row = blockIdx.x, tid = threadIdx.x;
    const int lane = tid & 31, wid = tid >> 5;
    const float* __restrict__ hrow = g_h + (size_t)row * HDIM_;

    float v[8]; unsigned u[8];
    *(float4*)&v[0] = *(const float4*)&hrow[tid * 8];
    *(float4*)&v[4] = *(const float4*)&hrow[tid * 8 + 4];
#pragma unroll
    for (int j = 0; j < 8; ++j) u[j] = __float_as_uint(v[j] * v[j]);

    unsigned T[2], R[2];
#pragma unroll 1
    for (int sel = 0; sel < 2; ++sel) {
        unsigned kk = sel ? 256u : 512u;
        unsigned prefix = 0u, pmask = 0u;
#pragma unroll 1
        for (int pass = 0; pass < 4; ++pass) {
            const int shift = 24 - 8 * pass;
            s_hist[tid] = 0u;
            __syncthreads();
#pragma unroll
            for (int j = 0; j < 8; ++j)
                if ((u[j] & pmask) == prefix)
                    atomicAdd(&s_hist[(u[j] >> shift) & 255u], 1u);
            __syncthreads();
            const unsigned cnt = s_hist[tid];
            unsigned suf = cnt;
#pragma unroll
            for (int off = 1; off < 32; off <<= 1) {
                unsigned t = __shfl_down_sync(0xffffffffu, suf, off);
                if (lane + off < 32) suf += t;
            }
            const unsigned wtot = __shfl_sync(0xffffffffu, suf, 0);
            if (lane == 0) s_warp[wid] = wtot;
            __syncthreads();
            if (tid < 8) {
                unsigned s = 0;
                for (int w = tid + 1; w < 8; ++w) s += s_warp[w];
                s_wsuf[tid] = s;
            }
            __syncthreads();
            suf += s_wsuf[wid];
            if (suf >= kk && suf - cnt < kk) {
                s_pick[0] = (unsigned)tid;
                s_pick[1] = kk - (suf - cnt);
            }
            __syncthreads();
            prefix |= s_pick[0] << shift;
            pmask  |= 255u << shift;
            kk = s_pick[1];
        }
        T[sel] = prefix;
        R[sel] = kk;
        __syncthreads();
    }

    unsigned c0 = 0, c1 = 0;
#pragma unroll
    for (int j = 0; j < 8; ++j) { c0 += (u[j] == T[0]); c1 += (u[j] == T[1]); }
    unsigned inc = (c0 << 16) | c1;
#pragma unroll
    for (int off = 1; off < 32; off <<= 1) {
        unsigned t = __shfl_up_sync(0xffffffffu, inc, off);
        if (lane >= off) inc += t;
    }
    if (lane == 31) s_warp[wid] = inc;
    __syncthreads();
    unsigned wpre = 0;
    for (int w = 0; w < 8; ++w) if (w < wid) wpre += s_warp[w];
    inc += wpre;
    unsigned r0 = (inc >> 16)     - c0;
    unsigned r1 = (inc & 0xFFFFu) - c1;

    const int* __restrict__ mrow = maskPrev + (size_t)row * HDIM_;
    float* __restrict__ nrow = maskNew + (size_t)row * HDIM_;
    __nv_bfloat16* __restrict__ hb0 = g_hb0 + (size_t)row * HDIM_;
    __nv_bfloat16* __restrict__ hb1 = g_hb1 + (size_t)row * HDIM_;

    int mp[8];
    *(int4*)&mp[0] = *(const int4*)&mrow[tid * 8];
    *(int4*)&mp[4] = *(const int4*)&mrow[tid * 8 + 4];

    __nv_bfloat16 b0[8], b1[8];
    float mn[8];
#pragma unroll
    for (int j = 0; j < 8; ++j) {
        const unsigned eq0 = (u[j] == T[0]) ? 1u : 0u;
        const bool share = (u[j] > T[0]) || (eq0 && r0 < R[0]);
        r0 += eq0;
        const unsigned eq1 = (u[j] == T[1]) ? 1u : 0u;
        const bool cur = (u[j] > T[1]) || (eq1 && r1 < R[1]);
        r1 += eq1;
        const float mv = share ? v[j] : 0.f;
        b0[j] = __float2bfloat16_rn(mv);
        b1[j] = __float2bfloat16_rn(mv - __bfloat162float(b0[j]));
        mn[j] = (float)mp[j] + (cur ? 1.f : 0.f);
    }
    *(uint4*)&hb0[tid * 8]       = *(uint4*)b0;
    *(uint4*)&hb1[tid * 8]       = *(uint4*)b1;
    *(float4*)&nrow[tid * 8]     = *(float4*)&mn[0];
    *(float4*)&nrow[tid * 8 + 4] = *(float4*)&mn[4];
}

extern "C" void kernel_launch(void* const* d_in, const int* in_sizes, int n_in,
                              void* d_out, int out_size)
{
    const float* x      = (const float*)d_in[0];
    const int*   mask_p = (const int*)  d_in[1];
    const float* W_enc  = (const float*)d_in[2];
    const float* b_enc  = (const float*)d_in[3];
    const float* W_dec  = (const float*)d_in[4];
    const float* b_dec  = (const float*)d_in[5];

    float* out      = (float*)d_out;
    float* mask_new = out + (size_t)M_TOT * ODIM_;

    float* hbuf;
    __nv_bfloat16 *hb0, *hb1, *wd0, *wd1;
    cudaGetSymbolAddress((void**)&hbuf, g_h);
    cudaGetSymbolAddress((void**)&hb0,  g_hb0);
    cudaGetSymbolAddress((void**)&hb1,  g_hb1);
    cudaGetSymbolAddress((void**)&wd0,  g_wd0);
    cudaGetSymbolAddress((void**)&wd1,  g_wd1);

    cudaFuncSetAttribute(gemm_bf4, cudaFuncAttributeMaxDynamicSharedMemorySize, SMEM_DEC);

    // split W_dec into 2 bf16 planes
    const int n8wd = ODIM_ * HDIM_ / 8;
    split_bf2<<<(n8wd + 255) / 256, 256>>>(W_dec, wd0, wd1, n8wd);

    // encoder (fp32 FFMA, exact numerics for top-k) + fused mask_prev zeroing
    sgemm_nt_mask<<<dim3(HDIM_ / 128, M_TOT / 128), 256>>>(
        x, W_enc, b_enc, mask_p, hbuf, M_TOT, HDIM_, IDIM_);

    // top-k masks + masked-h bf16 split + mask_prev_new
    topk_mask_kernel<<<M_TOT, 256>>>(mask_p, mask_new);

    // decoder (bf16 4-product tensor-core GEMM)
    gemm_bf4<<<dim3(ODIM_ / 128, M_TOT / 128), 256, SMEM_DEC>>>(
        hb0, hb1, wd0, wd1, b_dec, out, M_TOT, ODIM_, HDIM_);
}

// round 6
// speedup vs baseline: 1.5204x; 1.0001x over previous
#include <cuda_runtime.h>
#include <cuda_bf16.h>
#include <stdint.h>

#define M_TOT 16384
#define HDIM_ 2048
#define IDIM_ 512
#define ODIM_ 512

// scratch (device globals; no allocs allowed)
__device__ float         g_h  [(size_t)M_TOT * HDIM_];
__device__ __nv_bfloat16 g_hb0[(size_t)M_TOT * HDIM_];
__device__ __nv_bfloat16 g_hb1[(size_t)M_TOT * HDIM_];
__device__ __nv_bfloat16 g_wd0[(size_t)ODIM_ * HDIM_];
__device__ __nv_bfloat16 g_wd1[(size_t)ODIM_ * HDIM_];

__device__ __forceinline__ uint32_t smem_u32(const void* p){
    uint32_t a;
    asm("{ .reg .u64 t; cvta.to.shared.u64 t, %1; cvt.u32.u64 %0, t; }" : "=r"(a) : "l"(p));
    return a;
}
#define CP16(d, s) asm volatile("cp.async.cg.shared.global [%0], [%1], 16;" :: "r"(d), "l"(s))
#define CP_COMMIT() asm volatile("cp.async.commit_group;")
#define CP_WAIT1()  asm volatile("cp.async.wait_group 1;")

// ---------------------------------------------------------------------------
// Encoder: R1's FFMA SGEMM (known-good numerics for the top-k).
// C[M,N] = A[M,K] * B[N,K]^T + bias[N], zero where maskPrev>0.
// ---------------------------------------------------------------------------
__global__ __launch_bounds__(256)
void sgemm_nt_mask(const float* __restrict__ A,
                   const float* __restrict__ B,
                   const float* __restrict__ bias,
                   const int*   __restrict__ maskPrev,
                   float* __restrict__ C,
                   int M, int N, int K)
{
    __shared__ float As[16][128];
    __shared__ float Bs[16][128];

    const int tid = threadIdx.x;
    const int m0 = blockIdx.y * 128;
    const int n0 = blockIdx.x * 128;
    const int tx = tid & 15;
    const int ty = tid >> 4;

    float acc[8][8];
#pragma unroll
    for (int i = 0; i < 8; ++i)
#pragma unroll
        for (int j = 0; j < 8; ++j) acc[i][j] = 0.f;

    const float* Ab = A + (size_t)m0 * K;
    const float* Bb = B + (size_t)n0 * K;

    const int lrow = tid >> 2;
    const int lk   = (tid & 3) << 2;

    for (int kt = 0; kt < K; kt += 16) {
        float4 a0 = *(const float4*)(Ab + (size_t)lrow        * K + kt + lk);
        float4 a1 = *(const float4*)(Ab + (size_t)(lrow + 64) * K + kt + lk);
        float4 b0 = *(const float4*)(Bb + (size_t)lrow        * K + kt + lk);
        float4 b1 = *(const float4*)(Bb + (size_t)(lrow + 64) * K + kt + lk);

        As[lk + 0][lrow] = a0.x; As[lk + 1][lrow] = a0.y;
        As[lk + 2][lrow] = a0.z; As[lk + 3][lrow] = a0.w;
        As[lk + 0][lrow + 64] = a1.x; As[lk + 1][lrow + 64] = a1.y;
        As[lk + 2][lrow + 64] = a1.z; As[lk + 3][lrow + 64] = a1.w;
        Bs[lk + 0][lrow] = b0.x; Bs[lk + 1][lrow] = b0.y;
        Bs[lk + 2][lrow] = b0.z; Bs[lk + 3][lrow] = b0.w;
        Bs[lk + 0][lrow + 64] = b1.x; Bs[lk + 1][lrow + 64] = b1.y;
        Bs[lk + 2][lrow + 64] = b1.z; Bs[lk + 3][lrow + 64] = b1.w;
        __syncthreads();

#pragma unroll
        for (int k = 0; k < 16; ++k) {
            float a[8], b[8];
            *(float4*)&a[0] = *(const float4*)&As[k][ty * 8];
            *(float4*)&a[4] = *(const float4*)&As[k][ty * 8 + 4];
            *(float4*)&b[0] = *(const float4*)&Bs[k][tx * 8];
            *(float4*)&b[4] = *(const float4*)&Bs[k][tx * 8 + 4];
#pragma unroll
            for (int i = 0; i < 8; ++i)
#pragma unroll
                for (int j = 0; j < 8; ++j)
                    acc[i][j] = fmaf(a[i], b[j], acc[i][j]);
        }
        __syncthreads();
    }

    float bcol[8];
#pragma unroll
    for (int j = 0; j < 8; ++j) bcol[j] = bias[n0 + tx * 8 + j];

#pragma unroll
    for (int i = 0; i < 8; ++i) {
        const size_t m = (size_t)(m0 + ty * 8 + i);
#pragma unroll
        for (int jq = 0; jq < 8; jq += 4) {
            float4 v;
            v.x = acc[i][jq + 0] + bcol[jq + 0];
            v.y = acc[i][jq + 1] + bcol[jq + 1];
            v.z = acc[i][jq + 2] + bcol[jq + 2];
            v.w = acc[i][jq + 3] + bcol[jq + 3];
            const size_t cidx = m * (size_t)N + (size_t)(n0 + tx * 8 + jq);
            const int4 mp = *(const int4*)(maskPrev + cidx);
            if (mp.x > 0) v.x = 0.f;
            if (mp.y > 0) v.y = 0.f;
            if (mp.z > 0) v.z = 0.f;
            if (mp.w > 0) v.w = 0.f;
            *(float4*)(C + cidx) = v;
        }
    }
}

// ---------------------------------------------------------------------------
// Decoder: bf16 4-product mma.sync (m16n8k16). Inputs are exact 2-plane bf16
// splits (x = b0 + b1 + O(2^-16 x)); products b0b0+b0b1+b1b0+b1b1 -> ~3e-5 err.
// C[M,N] = A[M,K]*B[N,K]^T + bias[N].
// ---------------------------------------------------------------------------
__device__ __forceinline__ void mma_bf16(float* c, const uint32_t* a, uint32_t b0, uint32_t b1){
    asm volatile("mma.sync.aligned.m16n8k16.row.col.f32.bf16.bf16.f32 "
        "{%0,%1,%2,%3},{%4,%5,%6,%7},{%8,%9},{%0,%1,%2,%3};"
        : "+f"(c[0]), "+f"(c[1]), "+f"(c[2]), "+f"(c[3])
        : "r"(a[0]), "r"(a[1]), "r"(a[2]), "r"(a[3]), "r"(b0), "r"(b1));
}

static constexpr int LDTH    = 40;            // halfs per smem row (32 + 8 pad) -> conflict-free
static constexpr int PLANE_H = 128 * LDTH;    // 5120 halfs
static constexpr int PLANE_B = PLANE_H * 2;   // 10240 bytes
static constexpr int STAGE_B = 4 * PLANE_B;   // planes A0,A1,B0,B1 = 40960 bytes
static constexpr int BIAS_B  = 2 * STAGE_B;   // 81920
static constexpr int SMEM_DEC = BIAS_B + 512; // + 128 floats bias

__global__ __launch_bounds__(256, 1)
void gemm_bf4(const __nv_bfloat16* __restrict__ A0, const __nv_bfloat16* __restrict__ A1,
              const __nv_bfloat16* __restrict__ B0, const __nv_bfloat16* __restrict__ B1,
              const float* __restrict__ bias, float* __restrict__ C,
              int M, int N, int K)
{
    extern __shared__ char smem[];
    const uint32_t sb = smem_u32(smem);
    const int tid = threadIdx.x;
    const int lane = tid & 31, wid = tid >> 5;
    const int wm = wid & 3, wn = wid >> 2;        // 4 m-warps x 2 n-warps (tile 32x64)
    const int g = lane >> 2, t4 = lane & 3;
    const int m0 = blockIdx.y * 128, n0 = blockIdx.x * 128;

    float* sbias = (float*)(smem + BIAS_B);
    if (tid < 128) sbias[tid] = bias[n0 + tid];

    // staging: thread -> row = tid>>1, 32-byte half-chunk = (tid&1)
    const int lr  = tid >> 1;
    const int lcb = (tid & 1) * 32;               // byte offset in the 64B row chunk
    const __nv_bfloat16* pA0 = A0 + (size_t)(m0 + lr) * K;
    const __nv_bfloat16* pA1 = A1 + (size_t)(m0 + lr) * K;
    const __nv_bfloat16* pB0 = B0 + (size_t)(n0 + lr) * K;
    const __nv_bfloat16* pB1 = B1 + (size_t)(n0 + lr) * K;
    const uint32_t dof = (uint32_t)(lr * (LDTH * 2) + lcb);

    auto load_stage = [&](int kt, int s) {
        const uint32_t base = sb + (uint32_t)(s * STAGE_B) + dof;
        const int ko = kt * 32 + (lcb >> 1);      // half offset
        CP16(base,                 pA0 + ko); CP16(base + 16,                 pA0 + ko + 8);
        CP16(base + PLANE_B,       pA1 + ko); CP16(base + PLANE_B + 16,       pA1 + ko + 8);
        CP16(base + 2 * PLANE_B,   pB0 + ko); CP16(base + 2 * PLANE_B + 16,   pB0 + ko + 8);
        CP16(base + 3 * PLANE_B,   pB1 + ko); CP16(base + 3 * PLANE_B + 16,   pB1 + ko + 8);
    };

    float acc[2][8][4];
#pragma unroll
    for (int a = 0; a < 2; ++a)
#pragma unroll
        for (int b = 0; b < 8; ++b)
#pragma unroll
            for (int q = 0; q < 4; ++q) acc[a][b][q] = 0.f;

    load_stage(0, 0); CP_COMMIT();
    load_stage(1, 1); CP_COMMIT();

    const int KT = K >> 5;                        // 32-wide K chunks
    for (int kt = 0; kt < KT; ++kt) {
        const int s = kt & 1;
        CP_WAIT1();
        __syncthreads();
        const __nv_bfloat16* st = (const __nv_bfloat16*)(smem + s * STAGE_B);
#pragma unroll
        for (int ks = 0; ks < 2; ++ks) {
            uint32_t af[2][2][4];                 // [plane][mt][frag]
#pragma unroll
            for (int p = 0; p < 2; ++p)
#pragma unroll
                for (int mt = 0; mt < 2; ++mt) {
                    const int off = p * PLANE_H + (wm * 32 + mt * 16 + g) * LDTH + ks * 16 + 2 * t4;
                    af[p][mt][0] = *(const uint32_t*)(st + off);
                    af[p][mt][1] = *(const uint32_t*)(st + off + 8 * LDTH);
                    af[p][mt][2] = *(const uint32_t*)(st + off + 8);
                    af[p][mt][3] = *(const uint32_t*)(st + off + 8 * LDTH + 8);
                }
#pragma unroll
            for (int nt = 0; nt < 8; ++nt) {
                const int boff = (wn * 64 + nt * 8 + g) * LDTH + ks * 16 + 2 * t4;
                const uint32_t b00 = *(const uint32_t*)(st + 2 * PLANE_H + boff);
                const uint32_t b01 = *(const uint32_t*)(st + 2 * PLANE_H + boff + 8);
                const uint32_t b10 = *(const uint32_t*)(st + 3 * PLANE_H + boff);
                const uint32_t b11 = *(const uint32_t*)(st + 3 * PLANE_H + boff + 8);
#pragma unroll
                for (int mt = 0; mt < 2; ++mt) {
                    mma_bf16(acc[mt][nt], af[0][mt], b00, b01);
                    mma_bf16(acc[mt][nt], af[0][mt], b10, b11);
                    mma_bf16(acc[mt][nt], af[1][mt], b00, b01);
                    mma_bf16(acc[mt][nt], af[1][mt], b10, b11);
                }
            }
        }
        __syncthreads();
        if (kt + 2 < KT) load_stage(kt + 2, s);
        CP_COMMIT();
    }

#pragma unroll
    for (int mt = 0; mt < 2; ++mt) {
#pragma unroll
        for (int nt = 0; nt < 8; ++nt) {
            const int rr = m0 + wm * 32 + mt * 16 + g;
            const int cl = wn * 64 + nt * 8 + 2 * t4;
            const float b0 = sbias[cl];
            const float b1 = sbias[cl + 1];
            const float* c = acc[mt][nt];
            const size_t i0 = (size_t)rr * N + (n0 + cl);
            const size_t i1 = (size_t)(rr + 8) * N + (n0 + cl);
            *(float2*)(C + i0) = make_float2(c[0] + b0, c[1] + b1);
            *(float2*)(C + i1) = make_float2(c[2] + b0, c[3] + b1);
        }
    }
}

// fp32 -> 2-plane bf16 split (exact to 2^-16)
__global__ __launch_bounds__(256)
void split_bf2(const float* __restrict__ src, __nv_bfloat16* __restrict__ p0,
               __nv_bfloat16* __restrict__ p1, int n8)
{
    int i = blockIdx.x * 256 + threadIdx.x;
    if (i >= n8) return;
    float4 v0 = ((const float4*)src)[2 * i];
    float4 v1 = ((const float4*)src)[2 * i + 1];
    float x[8] = {v0.x, v0.y, v0.z, v0.w, v1.x, v1.y, v1.z, v1.w};
    __nv_bfloat16 b0[8], b1[8];
#pragma unroll
    for (int j = 0; j < 8; ++j) {
        b0[j] = __float2bfloat16_rn(x[j]);
        b1[j] = __float2bfloat16_rn(x[j] - __bfloat162float(b0[j]));
    }
    ((uint4*)p0)[i] = *(uint4*)b0;
    ((uint4*)p1)[i] = *(uint4*)b1;
}

// ---------------------------------------------------------------------------
// Per-row exact dual top-k (512/256) over h^2; radix select on bits of v*v,
// lowest-index tie break. Emits mask_new and masked-h as 2 bf16 planes.
// ---------------------------------------------------------------------------
__global__ __launch_bounds__(256)
void topk_mask_kernel(const int* __restrict__ maskPrev, float* __restrict__ maskNew)
{
    __shared__ unsigned s_hist[256];
    __shared__ unsigned s_warp[8];
    __shared__ unsigned s_wsuf[8];
    __shared__ unsigned s_pick[2];

    const int row = blockIdx.x, tid = threadIdx.x;
    const int lane = tid & 31, wid = tid >> 5;
    const float* __restrict__ hrow = g_h + (size_t)row * HDIM_;

    float v[8]; unsigned u[8];
    *(float4*)&v[0] = *(const float4*)&hrow[tid * 8];
    *(float4*)&v[4] = *(const float4*)&hrow[tid * 8 + 4];
#pragma unroll
    for (int j = 0; j < 8; ++j) u[j] = __float_as_uint(v[j] * v[j]);

    unsigned T[2], R[2];
#pragma unroll 1
    for (int sel = 0; sel < 2; ++sel) {
        unsigned kk = sel ? 256u : 512u;
        unsigned prefix = 0u, pmask = 0u;
#pragma unroll 1
        for (int pass = 0; pass < 4; ++pass) {
            const int shift = 24 - 8 * pass;
            s_hist[tid] = 0u;
            __syncthreads();
#pragma unroll
            for (int j = 0; j < 8; ++j)
                if ((u[j] & pmask) == prefix)
                    atomicAdd(&s_hist[(u[j] >> shift) & 255u], 1u);
            __syncthreads();
            const unsigned cnt = s_hist[tid];
            unsigned suf = cnt;
#pragma unroll
            for (int off = 1; off < 32; off <<= 1) {
                unsigned t = __shfl_down_sync(0xffffffffu, suf, off);
                if (lane + off < 32) suf += t;
            }
            const unsigned wtot = __shfl_sync(0xffffffffu, suf, 0);
            if (lane == 0) s_warp[wid] = wtot;
            __syncthreads();
            if (tid < 8) {
                unsigned s = 0;
                for (int w = tid + 1; w < 8; ++w) s += s_warp[w];
                s_wsuf[tid] = s;
            }
            __syncthreads();
            suf += s_wsuf[wid];
            if (suf >= kk && suf - cnt < kk) {
                s_pick[0] = (unsigned)tid;
                s_pick[1] = kk - (suf - cnt);
            }
            __syncthreads();
            prefix |= s_pick[0] << shift;
            pmask  |= 255u << shift;
            kk = s_pick[1];
        }
        T[sel] = prefix;
        R[sel] = kk;
        __syncthreads();
    }

    unsigned c0 = 0, c1 = 0;
#pragma unroll
    for (int j = 0; j < 8; ++j) { c0 += (u[j] == T[0]); c1 += (u[j] == T[1]); }
    unsigned inc = (c0 << 16) | c1;
#pragma unroll
    for (int off = 1; off < 32; off <<= 1) {
        unsigned t = __shfl_up_sync(0xffffffffu, inc, off);
        if (lane >= off) inc += t;
    }
    if (lane == 31) s_warp[wid] = inc;
    __syncthreads();
    unsigned wpre = 0;
    for (int w = 0; w < 8; ++w) if (w < wid) wpre += s_warp[w];
    inc += wpre;
    unsigned r0 = (inc >> 16)     - c0;
    unsigned r1 = (inc & 0xFFFFu) - c1;

    const int* __restrict__ mrow = maskPrev + (size_t)row * HDIM_;
    float* __restrict__ nrow = maskNew + (size_t)row * HDIM_;
    __nv_bfloat16* __restrict__ hb0 = g_hb0 + (size_t)row * HDIM_;
    __nv_bfloat16* __restrict__ hb1 = g_hb1 + (size_t)row * HDIM_;

    int mp[8];
    *(int4*)&mp[0] = *(const int4*)&mrow[tid * 8];
    *(int4*)&mp[4] = *(const int4*)&mrow[tid * 8 + 4];

    __nv_bfloat16 b0[8], b1[8];
    float mn[8];
#pragma unroll
    for (int j = 0; j < 8; ++j) {
        const unsigned eq0 = (u[j] == T[0]) ? 1u : 0u;
        const bool share = (u[j] > T[0]) || (eq0 && r0 < R[0]);
        r0 += eq0;
        const unsigned eq1 = (u[j] == T[1]) ? 1u : 0u;
        const bool cur = (u[j] > T[1]) || (eq1 && r1 < R[1]);
        r1 += eq1;
        const float mv = share ? v[j] : 0.f;
        b0[j] = __float2bfloat16_rn(mv);
        b1[j] = __float2bfloat16_rn(mv - __bfloat162float(b0[j]));
        mn[j] = (float)mp[j] + (cur ? 1.f : 0.f);
    }
    *(uint4*)&hb0[tid * 8]       = *(uint4*)b0;
    *(uint4*)&hb1[tid * 8]       = *(uint4*)b1;
    *(float4*)&nrow[tid * 8]     = *(float4*)&mn[0];
    *(float4*)&nrow[tid * 8 + 4] = *(float4*)&mn[4];
}

extern "C" void kernel_launch(void* const* d_in, const int* in_sizes, int n_in,
                              void* d_out, int out_size)
{
    const float* x      = (const float*)d_in[0];
    const int*   mask_p = (const int*)  d_in[1];
    const float* W_enc  = (const float*)d_in[2];
    const float* b_enc  = (const float*)d_in[3];
    const float* W_dec  = (const float*)d_in[4];
    const float* b_dec  = (const float*)d_in[5];

    float* out      = (float*)d_out;
    float* mask_new = out + (size_t)M_TOT * ODIM_;

    float* hbuf;
    __nv_bfloat16 *hb0, *hb1, *wd0, *wd1;
    cudaGetSymbolAddress((void**)&hbuf, g_h);
    cudaGetSymbolAddress((void**)&hb0,  g_hb0);
    cudaGetSymbolAddress((void**)&hb1,  g_hb1);
    cudaGetSymbolAddress((void**)&wd0,  g_wd0);
    cudaGetSymbolAddress((void**)&wd1,  g_wd1);

    cudaFuncSetAttribute(gemm_bf4, cudaFuncAttributeMaxDynamicSharedMemorySize, SMEM_DEC);

    // split W_dec into 2 bf16 planes
    const int n8wd = ODIM_ * HDIM_ / 8;
    split_bf2<<<(n8wd + 255) / 256, 256>>>(W_dec, wd0, wd1, n8wd);

    // encoder (fp32 FFMA, exact numerics for top-k) + fused mask_prev zeroing
    sgemm_nt_mask<<<dim3(HDIM_ / 128, M_TOT / 128), 256>>>(
        x, W_enc, b_enc, mask_p, hbuf, M_TOT, HDIM_, IDIM_);

    // top-k masks + masked-h bf16 split + mask_prev_new
    topk_mask_kernel<<<M_TOT, 256>>>(mask_p, mask_new);

    // decoder (bf16 4-product tensor-core GEMM)
    gemm_bf4<<<dim3(ODIM_ / 128, M_TOT / 128), 256, SMEM_DEC>>>(
        hb0, hb1, wd0, wd1, b_dec, out, M_TOT, ODIM_, HDIM_);
}